// round 7
// baseline (speedup 1.0000x reference)
#include <cuda_runtime.h>
#include <cuda_bf16.h>
#include <cstdint>

#define N_NODES 50000
#define N_EDGES 600000
#define DIM 128
#define CAP 64
#define OVMAX 8192

// Device scratch (zero-init at load; invariants restored each call)
__device__ float g_deg[N_NODES];                    // reset in k_dinv
__device__ float g_dinv[N_NODES];
__device__ float g_y[(size_t)N_NODES * DIM];        // y = x @ W^T
__device__ int   g_cnt[N_NODES];                    // reset in k_aggregate
__device__ int2  g_ebuck[(size_t)N_NODES * CAP];    // (src, bits(w)) per target bucket
__device__ int   g_ovcnt;                           // overflow counter (reset in k_dinv)
__device__ int   g_ovuse;                           // latched count for aggregate
__device__ int   g_ovt[OVMAX];
__device__ int2  g_ovsw[OVMAX];

typedef unsigned long long u64;

__device__ __forceinline__ void fma2(u64& d, u64 a, u64 b) {
    asm("fma.rn.f32x2 %0, %1, %2, %0;" : "+l"(d) : "l"(a), "l"(b));
}
__device__ __forceinline__ float2 up2(u64 v) {
    float2 f;
    asm("mov.b64 {%0, %1}, %2;" : "=f"(f.x), "=f"(f.y) : "l"(v));
    return f;
}

// =====================================================================
// Kernel A (fused): blocks [0,GB) = GEMM y = x@W^T
//                   blocks [GB,GB+EB) = edge pass (detect + deg + buckets)
// GEMM: BM=128, BN=128, BK=16, 256 threads, 8x8 microtile.
// Inner loop is pure 6x LDS.128 + 32x FFMA2 (f32x2):
//   - acc pairs span (m, m+1): A fragment LDS.128 = 2 natural f32x2 pairs
//   - B stored DUPLICATED in smem: LDS.128 = (b_n,b_n,b_n1,b_n1) = 2 pairs
// =====================================================================
#define PITCHA 132
#define PITCHB 256
__global__ __launch_bounds__(256, 2) void k_fused(const float* __restrict__ x,
                                                  const float* __restrict__ W,
                                                  const void* __restrict__ ei,
                                                  const float* __restrict__ ew,
                                                  int M, int E, int GB, int EB) {
    if ((int)blockIdx.x < GB) {
        __shared__ float As[16 * PITCHA];    // As[k][m]           8448 B
        __shared__ float Bsd[16 * PITCHB];   // Bsd[k][2n dup]    16384 B

        int tid = threadIdx.x;
        int tx = tid & 15;              // n quad
        int ty = tid >> 4;              // m block of 8
        int rowBase = blockIdx.x * 128;

        // A-load mapping: 128 m x 16 k per tile; lmA=tid>>2 (0..63), kqA=tid&3
        int lmA = tid >> 2;
        int kqA = tid & 3;
        // B-load mapping: n = tid&127, k-half = tid>>7 (8 k each)
        int nB = tid & 127;
        int khB = tid >> 7;

        u64 acc[4][8];                  // [m-pair][n]; 64 regs
        #pragma unroll
        for (int a = 0; a < 4; a++)
            #pragma unroll
            for (int b2 = 0; b2 < 8; b2++) acc[a][b2] = 0ULL;

        float4 pA[2], pB[2];
        #pragma unroll
        for (int j = 0; j < 2; j++) {
            int gm = rowBase + lmA + j * 64;
            pA[j] = (gm < M) ? *(const float4*)(x + (size_t)gm * DIM + kqA * 4)
                             : make_float4(0.f, 0.f, 0.f, 0.f);
            pB[j] = *(const float4*)(W + (size_t)nB * DIM + khB * 8 + j * 4);
        }

        #pragma unroll
        for (int kt = 0; kt < DIM; kt += 16) {
            // A transpose store
            #pragma unroll
            for (int j = 0; j < 2; j++) {
                int m = lmA + j * 64;
                As[(kqA * 4 + 0) * PITCHA + m] = pA[j].x;
                As[(kqA * 4 + 1) * PITCHA + m] = pA[j].y;
                As[(kqA * 4 + 2) * PITCHA + m] = pA[j].z;
                As[(kqA * 4 + 3) * PITCHA + m] = pA[j].w;
            }
            // B duplicated store: Bsd[k][2n] = Bsd[k][2n+1] = W[n][k]
            {
                float vb[8] = {pB[0].x, pB[0].y, pB[0].z, pB[0].w,
                               pB[1].x, pB[1].y, pB[1].z, pB[1].w};
                #pragma unroll
                for (int c = 0; c < 8; c++) {
                    *(float2*)&Bsd[(khB * 8 + c) * PITCHB + 2 * nB] =
                        make_float2(vb[c], vb[c]);
                }
            }
            __syncthreads();

            if (kt + 16 < DIM) {
                #pragma unroll
                for (int j = 0; j < 2; j++) {
                    int gm = rowBase + lmA + j * 64;
                    pA[j] = (gm < M) ? *(const float4*)(x + (size_t)gm * DIM + kt + 16 + kqA * 4)
                                     : make_float4(0.f, 0.f, 0.f, 0.f);
                    pB[j] = *(const float4*)(W + (size_t)nB * DIM + kt + 16 + khB * 8 + j * 4);
                }
            }

            #pragma unroll
            for (int k = 0; k < 16; k++) {
                ulonglong2 aA = *(const ulonglong2*)&As[k * PITCHA + ty * 8];
                ulonglong2 aB = *(const ulonglong2*)&As[k * PITCHA + ty * 8 + 4];
                ulonglong2 b0 = *(const ulonglong2*)&Bsd[k * PITCHB + 4 * tx];
                ulonglong2 b1 = *(const ulonglong2*)&Bsd[k * PITCHB + 64 + 4 * tx];
                ulonglong2 b2 = *(const ulonglong2*)&Bsd[k * PITCHB + 128 + 4 * tx];
                ulonglong2 b3 = *(const ulonglong2*)&Bsd[k * PITCHB + 192 + 4 * tx];
                u64 ap[4] = {aA.x, aA.y, aB.x, aB.y};
                u64 bp[8] = {b0.x, b0.y, b1.x, b1.y, b2.x, b2.y, b3.x, b3.y};
                #pragma unroll
                for (int mp = 0; mp < 4; mp++)
                    #pragma unroll
                    for (int nb = 0; nb < 8; nb++) fma2(acc[mp][nb], ap[mp], bp[nb]);
            }
            __syncthreads();
        }

        // Epilogue: acc[mp][nb] = (y[2mp][n], y[2mp+1][n]), n = (nb>>1)*32 + 2tx + (nb&1)
        #pragma unroll
        for (int mp = 0; mp < 4; mp++) {
            float2 p[8];
            #pragma unroll
            for (int nb = 0; nb < 8; nb++) p[nb] = up2(acc[mp][nb]);
            #pragma unroll
            for (int sub = 0; sub < 2; sub++) {
                int gm = rowBase + ty * 8 + 2 * mp + sub;
                if (gm < M) {
                    float* yrow = g_y + (size_t)gm * DIM;
                    #pragma unroll
                    for (int g = 0; g < 4; g++) {
                        float v0 = sub ? p[2 * g].y     : p[2 * g].x;
                        float v1 = sub ? p[2 * g + 1].y : p[2 * g + 1].x;
                        *(float2*)(yrow + g * 32 + 2 * tx) = make_float2(v0, v1);
                    }
                }
            }
        }
    } else {
        // ---------------- edge pass ----------------
        int b = blockIdx.x - GB;
        if (b >= EB) return;
        int chunk = (E + EB - 1) / EB;
        int beg = b * chunk;
        int end = beg + chunk; if (end > E) end = E;
        if (beg >= end) return;

        // per-block dtype detect on own chunk
        __shared__ int s_is64;
        if (threadIdx.x == 0) s_is64 = 1;
        __syncthreads();
        const long long* p64 = (const long long*)ei;
        const int*       p32 = (const int*)ei;
        int samp = end - beg; if (samp > 256) samp = 256;
        if ((int)threadIdx.x < samp) {
            long long v = p64[beg + threadIdx.x];
            if (v < 0 || v >= (long long)N_NODES) s_is64 = 0;
        }
        __syncthreads();
        int is64 = s_is64;

        for (int i = beg + threadIdx.x; i < end; i += 256) {
            int s, t;
            float w = ew[i];
            if (is64) { s = (int)p64[i]; t = (int)p64[(size_t)E + i]; }
            else      { s = p32[i];      t = p32[(size_t)E + i]; }
            atomicAdd(&g_deg[s], w);
            int pos = atomicAdd(&g_cnt[t], 1);
            if (pos < CAP) {
                g_ebuck[(size_t)t * CAP + pos] = make_int2(s, __float_as_int(w));
            } else {
                int o = atomicAdd(&g_ovcnt, 1);
                if (o < OVMAX) { g_ovt[o] = t; g_ovsw[o] = make_int2(s, __float_as_int(w)); }
            }
        }
    }
}

// ---------------- dinv = rsqrt(deg + 1); reset deg; latch overflow --------
__global__ void k_dinv(int n) {
    int i = blockIdx.x * blockDim.x + threadIdx.x;
    if (i < n) {
        g_dinv[i] = rsqrtf(g_deg[i] + 1.0f);   // +1 = self-loop
        g_deg[i] = 0.0f;
    }
    if (i == 0) {
        int c = g_ovcnt;
        g_ovuse = (c < OVMAX) ? c : OVMAX;
        g_ovcnt = 0;
    }
}

// ---------------- pull-aggregation: warp per node -------------------------
__global__ void k_aggregate(const float* __restrict__ bias,
                            float* __restrict__ out, int n) {
    int warp = (blockIdx.x * blockDim.x + threadIdx.x) >> 5;
    int lane = threadIdx.x & 31;
    if (warp >= n) return;
    int t = warp;

    int cnt = g_cnt[t];
    if (cnt > CAP) cnt = CAP;
    const float4* y4 = (const float4*)g_y;
    const int2* buck = g_ebuck + (size_t)t * CAP;

    float di = g_dinv[t];
    float sc = di * di;
    float4 self = y4[(size_t)t * 32 + lane];
    float4 bi = ((const float4*)bias)[lane];
    float4 acc;
    acc.x = self.x * sc + bi.x;
    acc.y = self.y * sc + bi.y;
    acc.z = self.z * sc + bi.z;
    acc.w = self.w * sc + bi.w;

    int2 e_nxt = make_int2(0, 0);
    if (cnt > 0) e_nxt = buck[0];
    for (int j = 0; j < cnt; j++) {
        int2 e = e_nxt;
        if (j + 1 < cnt) e_nxt = buck[j + 1];
        float wn = __int_as_float(e.y) * g_dinv[e.x] * di;
        float4 v = y4[(size_t)e.x * 32 + lane];
        acc.x += v.x * wn;
        acc.y += v.y * wn;
        acc.z += v.z * wn;
        acc.w += v.w * wn;
    }

    int ov = g_ovuse;
    for (int i = 0; i < ov; i++) {
        if (g_ovt[i] == t) {
            int2 e = g_ovsw[i];
            float wn = __int_as_float(e.y) * g_dinv[e.x] * di;
            float4 v = y4[(size_t)e.x * 32 + lane];
            acc.x += v.x * wn;
            acc.y += v.y * wn;
            acc.z += v.z * wn;
            acc.w += v.w * wn;
        }
    }

    ((float4*)out)[(size_t)t * 32 + lane] = acc;
    if (lane == 0) g_cnt[t] = 0;
}

extern "C" void kernel_launch(void* const* d_in, const int* in_sizes, int n_in,
                              void* d_out, int out_size) {
    const float* x  = (const float*)d_in[0];
    const void*  ei = d_in[1];
    const float* ew = (const float*)d_in[2];
    const float* W  = (const float*)d_in[3];
    const float* b  = (const float*)d_in[4];
    float* out = (float*)d_out;

    int N = in_sizes[0] / DIM;
    int E = in_sizes[1] / 2;

    int GB = (N + 127) / 128;
    int EB = 296;

    k_fused<<<GB + EB, 256>>>(x, W, ei, ew, N, E, GB, EB);
    k_dinv<<<(N + 255) / 256, 256>>>(N);
    k_aggregate<<<(N * 32 + 255) / 256, 256>>>(b, out, N);
}

// round 9
// speedup vs baseline: 1.0466x; 1.0466x over previous
#include <cuda_runtime.h>
#include <cuda_bf16.h>
#include <cstdint>

#define N_NODES 50000
#define N_EDGES 600000
#define DIM 128
#define CAP 64
#define OVMAX 8192

// Device scratch (zero-init at load; invariants restored each call)
__device__ float g_deg[N_NODES];                    // reset in k_dinv
__device__ float g_dinv[N_NODES];
__device__ float g_y[(size_t)N_NODES * DIM];        // y = x @ W^T
__device__ int   g_cnt[N_NODES];                    // reset in k_aggregate
__device__ int2  g_ebuck[(size_t)N_NODES * CAP];
__device__ int   g_ovcnt;
__device__ int   g_ovuse;
__device__ int   g_ovt[OVMAX];
__device__ int2  g_ovsw[OVMAX];

__device__ __forceinline__ uint32_t f2tf(float f) {
    uint32_t r;
    asm("cvt.rna.tf32.f32 %0, %1;" : "=r"(r) : "f"(f));
    return r;
}
__device__ __forceinline__ void mma1688(float& c0, float& c1, float& c2, float& c3,
                                        uint32_t a0, uint32_t a1, uint32_t a2, uint32_t a3,
                                        uint32_t b0, uint32_t b1) {
    asm volatile("mma.sync.aligned.m16n8k8.row.col.f32.tf32.tf32.f32 "
                 "{%0,%1,%2,%3}, {%4,%5,%6,%7}, {%8,%9}, {%0,%1,%2,%3};"
                 : "+f"(c0), "+f"(c1), "+f"(c2), "+f"(c3)
                 : "r"(a0), "r"(a1), "r"(a2), "r"(a3), "r"(b0), "r"(b1));
}

// =====================================================================
// Fused kernel: blocks [0,GB) = 3xTF32 tensor GEMM y = x@W^T (128-row tile)
//               blocks [GB,GB+EB) = edge pass (detect + deg + buckets)
// GEMM: 256 thr = 8 warps in 4(M) x 2(N) grid of 32x64 warp tiles.
// K chunked by 16; chunk staged once into hi/lo tf32 smem (pitch 20).
// =====================================================================
#define KC 16
#define SP 20
__global__ __launch_bounds__(256, 2) void k_fused(const float* __restrict__ x,
                                                  const float* __restrict__ W,
                                                  const void* __restrict__ ei,
                                                  const float* __restrict__ ew,
                                                  int M, int E, int GB, int EB) {
    if ((int)blockIdx.x < GB) {
        __shared__ uint32_t Ahi[128 * SP], Alo[128 * SP];
        __shared__ uint32_t Bhi[128 * SP], Blo[128 * SP];

        int tid = threadIdx.x;
        int lane = tid & 31;
        int wrp = tid >> 5;
        int wm = wrp & 3;               // M warp tile (32 rows)
        int wn = wrp >> 2;              // N warp tile (64 cols)
        int rowBase = blockIdx.x * 128;

        int g  = lane >> 2;             // group id 0..7
        int tg = lane & 3;              // thread-in-group 0..3

        float acc[2][8][4];
        #pragma unroll
        for (int mt = 0; mt < 2; mt++)
            #pragma unroll
            for (int nt = 0; nt < 8; nt++)
                #pragma unroll
                for (int c = 0; c < 4; c++) acc[mt][nt][c] = 0.0f;

        // staging mapping: idx = tid + j*256; row = idx>>2; q = idx&3
        int srow = tid >> 2;
        int sq   = tid & 3;

        float4 pA[2], pB[2];
        #pragma unroll
        for (int j = 0; j < 2; j++) {
            int row = srow + j * 64;
            int gm = rowBase + row;
            pA[j] = (gm < M) ? *(const float4*)(x + (size_t)gm * DIM + sq * 4)
                             : make_float4(0.f, 0.f, 0.f, 0.f);
            pB[j] = *(const float4*)(W + (size_t)row * DIM + sq * 4);
        }

        #pragma unroll
        for (int kt = 0; kt < DIM; kt += KC) {
            // stage chunk: convert to tf32 hi/lo, store pitch-20
            #pragma unroll
            for (int j = 0; j < 2; j++) {
                int row = srow + j * 64;
                float av[4] = {pA[j].x, pA[j].y, pA[j].z, pA[j].w};
                float bv[4] = {pB[j].x, pB[j].y, pB[j].z, pB[j].w};
                #pragma unroll
                for (int c = 0; c < 4; c++) {
                    uint32_t ah = f2tf(av[c]);
                    uint32_t bh = f2tf(bv[c]);
                    Ahi[row * SP + sq * 4 + c] = ah;
                    Alo[row * SP + sq * 4 + c] = f2tf(av[c] - __uint_as_float(ah));
                    Bhi[row * SP + sq * 4 + c] = bh;
                    Blo[row * SP + sq * 4 + c] = f2tf(bv[c] - __uint_as_float(bh));
                }
            }
            __syncthreads();

            if (kt + KC < DIM) {
                #pragma unroll
                for (int j = 0; j < 2; j++) {
                    int row = srow + j * 64;
                    int gm = rowBase + row;
                    pA[j] = (gm < M) ? *(const float4*)(x + (size_t)gm * DIM + kt + KC + sq * 4)
                                     : make_float4(0.f, 0.f, 0.f, 0.f);
                    pB[j] = *(const float4*)(W + (size_t)row * DIM + kt + KC + sq * 4);
                }
            }

            #pragma unroll
            for (int ks = 0; ks < 2; ks++) {
                int k0 = ks * 8;
                // A fragments: 2 m-tiles, hi+lo
                uint32_t ah[2][4], al[2][4];
                #pragma unroll
                for (int mt = 0; mt < 2; mt++) {
                    int r0 = (wm * 32 + mt * 16 + g) * SP + k0 + tg;
                    int r1 = r0 + 8 * SP;
                    ah[mt][0] = Ahi[r0];     ah[mt][1] = Ahi[r1];
                    ah[mt][2] = Ahi[r0 + 4]; ah[mt][3] = Ahi[r1 + 4];
                    al[mt][0] = Alo[r0];     al[mt][1] = Alo[r1];
                    al[mt][2] = Alo[r0 + 4]; al[mt][3] = Alo[r1 + 4];
                }
                #pragma unroll
                for (int nt = 0; nt < 8; nt++) {
                    int nb = (wn * 64 + nt * 8 + g) * SP + k0 + tg;
                    uint32_t bh0 = Bhi[nb], bh1 = Bhi[nb + 4];
                    uint32_t bl0 = Blo[nb], bl1 = Blo[nb + 4];
                    #pragma unroll
                    for (int mt = 0; mt < 2; mt++) {
                        float* c = acc[mt][nt];
                        mma1688(c[0], c[1], c[2], c[3],
                                ah[mt][0], ah[mt][1], ah[mt][2], ah[mt][3], bh0, bh1);
                        mma1688(c[0], c[1], c[2], c[3],
                                ah[mt][0], ah[mt][1], ah[mt][2], ah[mt][3], bl0, bl1);
                        mma1688(c[0], c[1], c[2], c[3],
                                al[mt][0], al[mt][1], al[mt][2], al[mt][3], bh0, bh1);
                    }
                }
            }
            __syncthreads();
        }

        // epilogue: write y
        #pragma unroll
        for (int mt = 0; mt < 2; mt++) {
            int row0 = rowBase + wm * 32 + mt * 16 + g;
            #pragma unroll
            for (int nt = 0; nt < 8; nt++) {
                int col = wn * 64 + nt * 8 + 2 * tg;
                float* c = acc[mt][nt];
                if (row0 < M)
                    *(float2*)(g_y + (size_t)row0 * DIM + col) = make_float2(c[0], c[1]);
                if (row0 + 8 < M)
                    *(float2*)(g_y + (size_t)(row0 + 8) * DIM + col) = make_float2(c[2], c[3]);
            }
        }
    } else {
        // ---------------- edge pass ----------------
        int b = blockIdx.x - GB;
        if (b >= EB) return;
        int chunk = (E + EB - 1) / EB;
        int beg = b * chunk;
        int end = beg + chunk; if (end > E) end = E;
        if (beg >= end) return;

        __shared__ int s_is64;
        if (threadIdx.x == 0) s_is64 = 1;
        __syncthreads();
        const long long* p64 = (const long long*)ei;
        const int*       p32 = (const int*)ei;
        int samp = end - beg; if (samp > 256) samp = 256;
        if ((int)threadIdx.x < samp) {
            long long v = p64[beg + threadIdx.x];
            if (v < 0 || v >= (long long)N_NODES) s_is64 = 0;
        }
        __syncthreads();
        int is64 = s_is64;

        for (int i = beg + threadIdx.x; i < end; i += 256) {
            int s, t;
            float w = ew[i];
            if (is64) { s = (int)p64[i]; t = (int)p64[(size_t)E + i]; }
            else      { s = p32[i];      t = p32[(size_t)E + i]; }
            atomicAdd(&g_deg[s], w);
            int pos = atomicAdd(&g_cnt[t], 1);
            if (pos < CAP) {
                g_ebuck[(size_t)t * CAP + pos] = make_int2(s, __float_as_int(w));
            } else {
                int o = atomicAdd(&g_ovcnt, 1);
                if (o < OVMAX) { g_ovt[o] = t; g_ovsw[o] = make_int2(s, __float_as_int(w)); }
            }
        }
    }
}

// ---------------- dinv = rsqrt(deg + 1); reset deg; latch overflow --------
__global__ void k_dinv(int n) {
    int i = blockIdx.x * blockDim.x + threadIdx.x;
    if (i < n) {
        g_dinv[i] = rsqrtf(g_deg[i] + 1.0f);
        g_deg[i] = 0.0f;
    }
    if (i == 0) {
        int c = g_ovcnt;
        g_ovuse = (c < OVMAX) ? c : OVMAX;
        g_ovcnt = 0;
    }
}

// ---------------- pull-aggregation: warp per node -------------------------
__global__ void k_aggregate(const float* __restrict__ bias,
                            float* __restrict__ out, int n) {
    int warp = (blockIdx.x * blockDim.x + threadIdx.x) >> 5;
    int lane = threadIdx.x & 31;
    if (warp >= n) return;
    int t = warp;

    int cnt = g_cnt[t];
    if (cnt > CAP) cnt = CAP;
    const float4* y4 = (const float4*)g_y;
    const int2* buck = g_ebuck + (size_t)t * CAP;

    float di = g_dinv[t];
    float sc = di * di;
    float4 self = y4[(size_t)t * 32 + lane];
    float4 bi = ((const float4*)bias)[lane];
    float4 acc;
    acc.x = self.x * sc + bi.x;
    acc.y = self.y * sc + bi.y;
    acc.z = self.z * sc + bi.z;
    acc.w = self.w * sc + bi.w;

    int2 e_nxt = make_int2(0, 0);
    if (cnt > 0) e_nxt = buck[0];
    for (int j = 0; j < cnt; j++) {
        int2 e = e_nxt;
        if (j + 1 < cnt) e_nxt = buck[j + 1];
        float wn = __int_as_float(e.y) * g_dinv[e.x] * di;
        float4 v = y4[(size_t)e.x * 32 + lane];
        acc.x += v.x * wn;
        acc.y += v.y * wn;
        acc.z += v.z * wn;
        acc.w += v.w * wn;
    }

    int ov = g_ovuse;
    for (int i = 0; i < ov; i++) {
        if (g_ovt[i] == t) {
            int2 e = g_ovsw[i];
            float wn = __int_as_float(e.y) * g_dinv[e.x] * di;
            float4 v = y4[(size_t)e.x * 32 + lane];
            acc.x += v.x * wn;
            acc.y += v.y * wn;
            acc.z += v.z * wn;
            acc.w += v.w * wn;
        }
    }

    ((float4*)out)[(size_t)t * 32 + lane] = acc;
    if (lane == 0) g_cnt[t] = 0;
}

extern "C" void kernel_launch(void* const* d_in, const int* in_sizes, int n_in,
                              void* d_out, int out_size) {
    const float* x  = (const float*)d_in[0];
    const void*  ei = d_in[1];
    const float* ew = (const float*)d_in[2];
    const float* W  = (const float*)d_in[3];
    const float* b  = (const float*)d_in[4];
    float* out = (float*)d_out;

    int N = in_sizes[0] / DIM;
    int E = in_sizes[1] / 2;

    int GB = (N + 127) / 128;
    int EB = 296;

    k_fused<<<GB + EB, 256>>>(x, W, ei, ew, N, E, GB, EB);
    k_dinv<<<(N + 255) / 256, 256>>>(N);
    k_aggregate<<<(N * 32 + 255) / 256, 256>>>(b, out, N);
}

// round 10
// speedup vs baseline: 1.1304x; 1.0800x over previous
#include <cuda_runtime.h>
#include <cuda_bf16.h>
#include <cstdint>

#define N_NODES 50000
#define N_EDGES 600000
#define DIM 128
#define CAP 64
#define OVMAX 8192

// Device scratch (zero-init at load; invariants restored each call)
__device__ float g_deg[N_NODES];                    // reset in k_dinv
__device__ float g_dinv[N_NODES];
__device__ float g_y[(size_t)N_NODES * DIM];        // y = x @ W^T
__device__ int   g_cnt[N_NODES];                    // reset in k_aggregate
__device__ int2  g_ebuck[(size_t)N_NODES * CAP];
__device__ int   g_ovcnt;
__device__ int   g_ovuse;
__device__ int   g_ovt[OVMAX];
__device__ int2  g_ovsw[OVMAX];

__device__ __forceinline__ void mma16816bf(float& c0, float& c1, float& c2, float& c3,
                                           uint32_t a0, uint32_t a1, uint32_t a2, uint32_t a3,
                                           uint32_t b0, uint32_t b1) {
    asm volatile("mma.sync.aligned.m16n8k16.row.col.f32.bf16.bf16.f32 "
                 "{%0,%1,%2,%3}, {%4,%5,%6,%7}, {%8,%9}, {%0,%1,%2,%3};"
                 : "+f"(c0), "+f"(c1), "+f"(c2), "+f"(c3)
                 : "r"(a0), "r"(a1), "r"(a2), "r"(a3), "r"(b0), "r"(b1));
}

// pack two floats to bf16x2 (hi), return residuals
__device__ __forceinline__ uint32_t pkh(float a, float b, float& ra, float& rb) {
    __nv_bfloat16 ha = __float2bfloat16(a);
    __nv_bfloat16 hb = __float2bfloat16(b);
    ra = a - __bfloat162float(ha);
    rb = b - __bfloat162float(hb);
    __nv_bfloat162 h2(ha, hb);
    return *(uint32_t*)&h2;
}
__device__ __forceinline__ uint32_t pk0(float a, float b) {
    __nv_bfloat162 h2(__float2bfloat16(a), __float2bfloat16(b));
    return *(uint32_t*)&h2;
}

// =====================================================================
// Fused kernel: blocks [0,EB) = edge pass (overlaps GEMM in wave 1)
//               blocks [EB,EB+GB) = split-bf16 tensor GEMM y = x@W^T
// GEMM: 256 thr = 8 warps in 4(M) x 2(N) grid of 32x64 warp tiles,
// K chunked by 16, m16n8k16 bf16 MMA, 3-term split (xh*Wh + xl*Wh + xh*Wl).
// Fragment smem pitch 12 words -> conflict-free LDS.
// =====================================================================
#define SP 12
__global__ __launch_bounds__(256, 2) void k_fused(const float* __restrict__ x,
                                                  const float* __restrict__ W,
                                                  const void* __restrict__ ei,
                                                  const float* __restrict__ ew,
                                                  int M, int E, int GB, int EB) {
    if ((int)blockIdx.x >= EB) {
        // ---------------- GEMM tile ----------------
        __shared__ uint32_t Ah[128 * SP], Al[128 * SP];
        __shared__ uint32_t Bh[128 * SP], Bl[128 * SP];

        int tid = threadIdx.x;
        int lane = tid & 31;
        int wrp = tid >> 5;
        int wm = wrp & 3;               // M warp tile (32 rows)
        int wn = wrp >> 2;              // N warp tile (64 cols)
        int rowBase = (blockIdx.x - EB) * 128;

        int g  = lane >> 2;             // 0..7
        int tg = lane & 3;              // 0..3

        float acc[2][8][4];
        #pragma unroll
        for (int mt = 0; mt < 2; mt++)
            #pragma unroll
            for (int nt = 0; nt < 8; nt++)
                #pragma unroll
                for (int c = 0; c < 4; c++) acc[mt][nt][c] = 0.0f;

        // staging: thread -> row = tid>>1, half = tid&1 (8 k-values each)
        int srow = tid >> 1;
        int shalf = tid & 1;
        int sbase = shalf * 4;          // word offset within row

        float4 pa0, pa1, pb0, pb1;
        {
            int gm = rowBase + srow;
            const float* xr = x + (size_t)gm * DIM + shalf * 8;
            const float* wr = W + (size_t)srow * DIM + shalf * 8;
            if (gm < M) { pa0 = *(const float4*)xr; pa1 = *(const float4*)(xr + 4); }
            else { pa0 = make_float4(0,0,0,0); pa1 = make_float4(0,0,0,0); }
            pb0 = *(const float4*)wr; pb1 = *(const float4*)(wr + 4);
        }

        #pragma unroll
        for (int kt = 0; kt < DIM; kt += 16) {
            // stage: convert f32 -> bf16 hi/lo pairs
            {
                float a[8] = {pa0.x, pa0.y, pa0.z, pa0.w, pa1.x, pa1.y, pa1.z, pa1.w};
                float b[8] = {pb0.x, pb0.y, pb0.z, pb0.w, pb1.x, pb1.y, pb1.z, pb1.w};
                int rw = srow * SP + sbase;
                #pragma unroll
                for (int i = 0; i < 4; i++) {
                    float r0, r1, s0, s1;
                    Ah[rw + i] = pkh(a[2 * i], a[2 * i + 1], r0, r1);
                    Al[rw + i] = pk0(r0, r1);
                    Bh[rw + i] = pkh(b[2 * i], b[2 * i + 1], s0, s1);
                    Bl[rw + i] = pk0(s0, s1);
                }
            }
            __syncthreads();

            if (kt + 16 < DIM) {
                int gm = rowBase + srow;
                const float* xr = x + (size_t)gm * DIM + kt + 16 + shalf * 8;
                const float* wr = W + (size_t)srow * DIM + kt + 16 + shalf * 8;
                if (gm < M) { pa0 = *(const float4*)xr; pa1 = *(const float4*)(xr + 4); }
                else { pa0 = make_float4(0,0,0,0); pa1 = make_float4(0,0,0,0); }
                pb0 = *(const float4*)wr; pb1 = *(const float4*)(wr + 4);
            }

            // fragments + MMA
            uint32_t ah[2][4], al[2][4];
            #pragma unroll
            for (int mt = 0; mt < 2; mt++) {
                int r0 = (wm * 32 + mt * 16 + g) * SP;
                int r1 = r0 + 8 * SP;
                ah[mt][0] = Ah[r0 + tg];     ah[mt][1] = Ah[r1 + tg];
                ah[mt][2] = Ah[r0 + tg + 4]; ah[mt][3] = Ah[r1 + tg + 4];
                al[mt][0] = Al[r0 + tg];     al[mt][1] = Al[r1 + tg];
                al[mt][2] = Al[r0 + tg + 4]; al[mt][3] = Al[r1 + tg + 4];
            }
            #pragma unroll
            for (int nt = 0; nt < 8; nt++) {
                int nb = (wn * 64 + nt * 8 + g) * SP;
                uint32_t bh0 = Bh[nb + tg], bh1 = Bh[nb + tg + 4];
                uint32_t bl0 = Bl[nb + tg], bl1 = Bl[nb + tg + 4];
                #pragma unroll
                for (int mt = 0; mt < 2; mt++) {
                    float* c = acc[mt][nt];
                    mma16816bf(c[0], c[1], c[2], c[3],
                               ah[mt][0], ah[mt][1], ah[mt][2], ah[mt][3], bh0, bh1);
                    mma16816bf(c[0], c[1], c[2], c[3],
                               ah[mt][0], ah[mt][1], ah[mt][2], ah[mt][3], bl0, bl1);
                    mma16816bf(c[0], c[1], c[2], c[3],
                               al[mt][0], al[mt][1], al[mt][2], al[mt][3], bh0, bh1);
                }
            }
            __syncthreads();
        }

        // epilogue: write y
        #pragma unroll
        for (int mt = 0; mt < 2; mt++) {
            int row0 = rowBase + wm * 32 + mt * 16 + g;
            #pragma unroll
            for (int nt = 0; nt < 8; nt++) {
                int col = wn * 64 + nt * 8 + 2 * tg;
                float* c = acc[mt][nt];
                if (row0 < M)
                    *(float2*)(g_y + (size_t)row0 * DIM + col) = make_float2(c[0], c[1]);
                if (row0 + 8 < M)
                    *(float2*)(g_y + (size_t)(row0 + 8) * DIM + col) = make_float2(c[2], c[3]);
            }
        }
    } else {
        // ---------------- edge pass (runs in first wave) ----------------
        int b = blockIdx.x;
        int chunk = (E + EB - 1) / EB;
        int beg = b * chunk;
        int end = beg + chunk; if (end > E) end = E;
        if (beg >= end) return;

        __shared__ int s_is64;
        if (threadIdx.x == 0) s_is64 = 1;
        __syncthreads();
        const long long* p64 = (const long long*)ei;
        const int*       p32 = (const int*)ei;
        int samp = end - beg; if (samp > 256) samp = 256;
        if ((int)threadIdx.x < samp) {
            long long v = p64[beg + threadIdx.x];
            if (v < 0 || v >= (long long)N_NODES) s_is64 = 0;
        }
        __syncthreads();
        int is64 = s_is64;

        for (int i = beg + threadIdx.x; i < end; i += 256) {
            int s, t;
            float w = ew[i];
            if (is64) { s = (int)p64[i]; t = (int)p64[(size_t)E + i]; }
            else      { s = p32[i];      t = p32[(size_t)E + i]; }
            atomicAdd(&g_deg[s], w);
            int pos = atomicAdd(&g_cnt[t], 1);
            if (pos < CAP) {
                g_ebuck[(size_t)t * CAP + pos] = make_int2(s, __float_as_int(w));
            } else {
                int o = atomicAdd(&g_ovcnt, 1);
                if (o < OVMAX) { g_ovt[o] = t; g_ovsw[o] = make_int2(s, __float_as_int(w)); }
            }
        }
    }
}

// ---------------- dinv = rsqrt(deg + 1); reset deg; latch overflow --------
__global__ void k_dinv(int n) {
    int i = blockIdx.x * blockDim.x + threadIdx.x;
    if (i < n) {
        g_dinv[i] = rsqrtf(g_deg[i] + 1.0f);
        g_deg[i] = 0.0f;
    }
    if (i == 0) {
        int c = g_ovcnt;
        g_ovuse = (c < OVMAX) ? c : OVMAX;
        g_ovcnt = 0;
    }
}

// ---------------- pull-aggregation: warp per node -------------------------
__global__ void k_aggregate(const float* __restrict__ bias,
                            float* __restrict__ out, int n) {
    int warp = (blockIdx.x * blockDim.x + threadIdx.x) >> 5;
    int lane = threadIdx.x & 31;
    if (warp >= n) return;
    int t = warp;

    int cnt = g_cnt[t];
    if (cnt > CAP) cnt = CAP;
    const float4* y4 = (const float4*)g_y;
    const int2* buck = g_ebuck + (size_t)t * CAP;

    float di = g_dinv[t];
    float sc = di * di;
    float4 self = y4[(size_t)t * 32 + lane];
    float4 bi = ((const float4*)bias)[lane];
    float4 acc;
    acc.x = self.x * sc + bi.x;
    acc.y = self.y * sc + bi.y;
    acc.z = self.z * sc + bi.z;
    acc.w = self.w * sc + bi.w;

    int2 e_nxt = make_int2(0, 0);
    if (cnt > 0) e_nxt = buck[0];
    for (int j = 0; j < cnt; j++) {
        int2 e = e_nxt;
        if (j + 1 < cnt) e_nxt = buck[j + 1];
        float wn = __int_as_float(e.y) * g_dinv[e.x] * di;
        float4 v = y4[(size_t)e.x * 32 + lane];
        acc.x += v.x * wn;
        acc.y += v.y * wn;
        acc.z += v.z * wn;
        acc.w += v.w * wn;
    }

    int ov = g_ovuse;
    for (int i = 0; i < ov; i++) {
        if (g_ovt[i] == t) {
            int2 e = g_ovsw[i];
            float wn = __int_as_float(e.y) * g_dinv[e.x] * di;
            float4 v = y4[(size_t)e.x * 32 + lane];
            acc.x += v.x * wn;
            acc.y += v.y * wn;
            acc.z += v.z * wn;
            acc.w += v.w * wn;
        }
    }

    ((float4*)out)[(size_t)t * 32 + lane] = acc;
    if (lane == 0) g_cnt[t] = 0;
}

extern "C" void kernel_launch(void* const* d_in, const int* in_sizes, int n_in,
                              void* d_out, int out_size) {
    const float* x  = (const float*)d_in[0];
    const void*  ei = d_in[1];
    const float* ew = (const float*)d_in[2];
    const float* W  = (const float*)d_in[3];
    const float* b  = (const float*)d_in[4];
    float* out = (float*)d_out;

    int N = in_sizes[0] / DIM;
    int E = in_sizes[1] / 2;

    int GB = (N + 127) / 128;
    int EB = 296;

    k_fused<<<GB + EB, 256>>>(x, W, ei, ew, N, E, GB, EB);
    k_dinv<<<(N + 255) / 256, 256>>>(N);
    k_aggregate<<<(N * 32 + 255) / 256, 256>>>(b, out, N);
}